// round 1
// baseline (speedup 1.0000x reference)
#include <cuda_runtime.h>
#include <cuda_bf16.h>
#include <math_constants.h>

// Problem constants
#define BB   4
#define NN   2048
#define DIM  1024
#define HH   16
#define HD   64
#define E3   (3 * DIM)          // 3072
#define MTOT (BB * NN)          // 8192
#define SCALE 0.125f            // 1/sqrt(64)

// Scratch: Q (pre-scaled), K, V in [B, H, N, HD] layout
__device__ float g_Q[BB * HH * NN * HD];
__device__ float g_K[BB * HH * NN * HD];
__device__ float g_V[BB * HH * NN * HD];

// ---------------------------------------------------------------------------
// Kernel 1: QKV GEMM. out[m][e] = sum_k x[m][k] * w[e][k] + bias[e]
// 128x128 tile, BK=8, 8x8 per thread, 256 threads.
// Epilogue scatters to g_Q (scaled), g_K, g_V.
// ---------------------------------------------------------------------------
__global__ __launch_bounds__(256) void qkv_gemm_kernel(
    const float* __restrict__ x,     // [8192, 1024]
    const float* __restrict__ w,     // [3072, 1024]
    const float* __restrict__ bias)  // [3072]
{
    __shared__ __align__(16) float As[8 * 128];  // [k][m]
    __shared__ __align__(16) float Bs[8 * 128];  // [k][e]

    const int tid = threadIdx.x;
    const int tx = tid & 15;         // col group
    const int ty = tid >> 4;         // row group
    const int m0 = blockIdx.y * 128;
    const int e0 = blockIdx.x * 128;

    // global load indices: each thread loads one float4 per tile per operand
    const int ldRow = tid >> 1;          // 0..127
    const int ldK   = (tid & 1) * 4;     // 0 or 4

    float acc[8][8];
#pragma unroll
    for (int i = 0; i < 8; i++)
#pragma unroll
        for (int j = 0; j < 8; j++) acc[i][j] = 0.0f;

    for (int kt = 0; kt < DIM; kt += 8) {
        float4 av = *(const float4*)&x[(size_t)(m0 + ldRow) * DIM + kt + ldK];
        float4 bv = *(const float4*)&w[(size_t)(e0 + ldRow) * DIM + kt + ldK];
        As[(ldK + 0) * 128 + ldRow] = av.x;
        As[(ldK + 1) * 128 + ldRow] = av.y;
        As[(ldK + 2) * 128 + ldRow] = av.z;
        As[(ldK + 3) * 128 + ldRow] = av.w;
        Bs[(ldK + 0) * 128 + ldRow] = bv.x;
        Bs[(ldK + 1) * 128 + ldRow] = bv.y;
        Bs[(ldK + 2) * 128 + ldRow] = bv.z;
        Bs[(ldK + 3) * 128 + ldRow] = bv.w;
        __syncthreads();

#pragma unroll
        for (int k = 0; k < 8; k++) {
            float a[8], b[8];
            float4 a0 = *(const float4*)&As[k * 128 + ty * 8];
            float4 a1 = *(const float4*)&As[k * 128 + ty * 8 + 4];
            float4 b0 = *(const float4*)&Bs[k * 128 + tx * 8];
            float4 b1 = *(const float4*)&Bs[k * 128 + tx * 8 + 4];
            a[0]=a0.x; a[1]=a0.y; a[2]=a0.z; a[3]=a0.w;
            a[4]=a1.x; a[5]=a1.y; a[6]=a1.z; a[7]=a1.w;
            b[0]=b0.x; b[1]=b0.y; b[2]=b0.z; b[3]=b0.w;
            b[4]=b1.x; b[5]=b1.y; b[6]=b1.z; b[7]=b1.w;
#pragma unroll
            for (int i = 0; i < 8; i++)
#pragma unroll
                for (int j = 0; j < 8; j++)
                    acc[i][j] = fmaf(a[i], b[j], acc[i][j]);
        }
        __syncthreads();
    }

    // Epilogue: bias + scatter to [B,H,N,HD] with Q pre-scaled.
#pragma unroll
    for (int j = 0; j < 8; j++) {
        const int e  = e0 + tx * 8 + j;
        const int t  = e >> 10;              // 0:Q 1:K 2:V
        const int h  = (e >> 6) & (HH - 1);
        const int hd = e & (HD - 1);
        const float be = bias[e];
        float* dst = (t == 0) ? g_Q : (t == 1) ? g_K : g_V;
        const float mul = (t == 0) ? SCALE : 1.0f;
#pragma unroll
        for (int i = 0; i < 8; i++) {
            const int m = m0 + ty * 8 + i;
            const int b = m >> 11;           // /NN
            const int n = m & (NN - 1);
            dst[(size_t)((b * HH + h) * NN + n) * HD + hd] = (acc[i][j] + be) * mul;
        }
    }
}

// ---------------------------------------------------------------------------
// Kernel 2: Flash attention, fp32. One block = one (b,h) and one 64-row q-tile.
// 256 threads; thread (ty,tx) owns a 4x4 patch of S/P[q][k] and of O[q][d].
// Smem: Qs [d][q], BufA = K [d][k] then P [k][q], BufB = V [k][d]. 48 KB total.
// ---------------------------------------------------------------------------
__global__ __launch_bounds__(256) void attn_kernel(float* __restrict__ out)
{
    __shared__ __align__(16) float Qs[64 * 64];
    __shared__ __align__(16) float BufA[64 * 64];
    __shared__ __align__(16) float BufB[64 * 64];

    const int tid = threadIdx.x;
    const int tx = tid & 15, ty = tid >> 4;
    const int r0 = ty * 4, c0 = tx * 4;

    const int qt = blockIdx.x;   // 0..31
    const int h  = blockIdx.y;
    const int b  = blockIdx.z;
    const int q0 = qt * 64;

    const size_t base = (size_t)((b * HH + h) * NN) * HD;
    const float* Qg = g_Q + base;
    const float* Kg = g_K + base;
    const float* Vg = g_V + base;

    // Load Q tile transposed: Qs[d][q]
#pragma unroll
    for (int i = 0; i < 4; i++) {
        int id = tid + i * 256;
        int q  = id >> 4;
        int d  = (id & 15) << 2;
        float4 v = *(const float4*)&Qg[(size_t)(q0 + q) * HD + d];
        Qs[(d + 0) * 64 + q] = v.x;
        Qs[(d + 1) * 64 + q] = v.y;
        Qs[(d + 2) * 64 + q] = v.z;
        Qs[(d + 3) * 64 + q] = v.w;
    }

    float m_i[4], l_i[4];
    float o[4][4];
#pragma unroll
    for (int i = 0; i < 4; i++) {
        m_i[i] = -CUDART_INF_F;
        l_i[i] = 0.0f;
#pragma unroll
        for (int j = 0; j < 4; j++) o[i][j] = 0.0f;
    }

    for (int kt = 0; kt < NN / 64; kt++) {
        const int k0 = kt * 64;
        // Load K transposed [d][k] into BufA, V natural [k][d] into BufB
#pragma unroll
        for (int i = 0; i < 4; i++) {
            int id = tid + i * 256;
            int r  = id >> 4;
            int d  = (id & 15) << 2;
            float4 kv = *(const float4*)&Kg[(size_t)(k0 + r) * HD + d];
            BufA[(d + 0) * 64 + r] = kv.x;
            BufA[(d + 1) * 64 + r] = kv.y;
            BufA[(d + 2) * 64 + r] = kv.z;
            BufA[(d + 3) * 64 + r] = kv.w;
            float4 vv = *(const float4*)&Vg[(size_t)(k0 + r) * HD + d];
            *(float4*)&BufB[r * 64 + d] = vv;
        }
        __syncthreads();

        // S = Q . K^T  (dot over d)
        float s[4][4];
#pragma unroll
        for (int i = 0; i < 4; i++)
#pragma unroll
            for (int j = 0; j < 4; j++) s[i][j] = 0.0f;

#pragma unroll 8
        for (int d = 0; d < 64; d++) {
            float4 qa = *(const float4*)&Qs[d * 64 + r0];
            float4 kb = *(const float4*)&BufA[d * 64 + c0];
            float a[4] = {qa.x, qa.y, qa.z, qa.w};
            float bb[4] = {kb.x, kb.y, kb.z, kb.w};
#pragma unroll
            for (int i = 0; i < 4; i++)
#pragma unroll
                for (int j = 0; j < 4; j++)
                    s[i][j] = fmaf(a[i], bb[j], s[i][j]);
        }
        __syncthreads();  // everyone done reading K before P overwrites BufA

        // Online softmax update
        float rm[4], rs[4], alpha[4];
#pragma unroll
        for (int i = 0; i < 4; i++) {
            float v = fmaxf(fmaxf(s[i][0], s[i][1]), fmaxf(s[i][2], s[i][3]));
#pragma unroll
            for (int off = 8; off >= 1; off >>= 1)
                v = fmaxf(v, __shfl_xor_sync(0xffffffffu, v, off));
            rm[i] = v;
            float mnew = fmaxf(m_i[i], v);
            alpha[i] = __expf(m_i[i] - mnew);
            m_i[i] = mnew;
        }
#pragma unroll
        for (int i = 0; i < 4; i++) {
            float sum = 0.0f;
#pragma unroll
            for (int j = 0; j < 4; j++) {
                s[i][j] = __expf(s[i][j] - m_i[i]);   // now P
                sum += s[i][j];
            }
#pragma unroll
            for (int off = 8; off >= 1; off >>= 1)
                sum += __shfl_xor_sync(0xffffffffu, sum, off);
            rs[i] = sum;
            l_i[i] = l_i[i] * alpha[i] + rs[i];
#pragma unroll
            for (int j = 0; j < 4; j++) o[i][j] *= alpha[i];
        }

        // Store P transposed into BufA as [k][q]
#pragma unroll
        for (int i = 0; i < 4; i++)
#pragma unroll
            for (int j = 0; j < 4; j++)
                BufA[(c0 + j) * 64 + (r0 + i)] = s[i][j];
        __syncthreads();

        // O += P . V   (sum over k)
#pragma unroll 8
        for (int k = 0; k < 64; k++) {
            float4 pv = *(const float4*)&BufA[k * 64 + r0];
            float4 vv = *(const float4*)&BufB[k * 64 + c0];
            float p[4] = {pv.x, pv.y, pv.z, pv.w};
            float v[4] = {vv.x, vv.y, vv.z, vv.w};
#pragma unroll
            for (int i = 0; i < 4; i++)
#pragma unroll
                for (int j = 0; j < 4; j++)
                    o[i][j] = fmaf(p[i], v[j], o[i][j]);
        }
        __syncthreads();  // before next tile overwrites BufA/BufB
    }

    // Write out: [B, N, H*HD]
#pragma unroll
    for (int i = 0; i < 4; i++) {
        const float inv = 1.0f / l_i[i];
        const int q = q0 + r0 + i;
        float4 res;
        res.x = o[i][0] * inv;
        res.y = o[i][1] * inv;
        res.z = o[i][2] * inv;
        res.w = o[i][3] * inv;
        *(float4*)&out[(size_t)(b * NN + q) * DIM + h * HD + c0] = res;
    }
}

// ---------------------------------------------------------------------------
extern "C" void kernel_launch(void* const* d_in, const int* in_sizes, int n_in,
                              void* d_out, int out_size)
{
    const float* x    = (const float*)d_in[0];
    const float* w    = (const float*)d_in[1];
    const float* bias = (const float*)d_in[2];
    float* out = (float*)d_out;

    dim3 g1(E3 / 128, MTOT / 128);   // 24 x 64
    qkv_gemm_kernel<<<g1, 256>>>(x, w, bias);

    dim3 g2(NN / 64, HH, BB);        // 32 x 16 x 4
    attn_kernel<<<g2, 256>>>(out);
}

// round 2
// speedup vs baseline: 1.0001x; 1.0001x over previous
#include <cuda_runtime.h>
#include <cuda_bf16.h>
#include <math_constants.h>

// Problem constants
#define BB   4
#define NN   2048
#define DIM  1024
#define HH   16
#define HD   64
#define E3   (3 * DIM)          // 3072
#define MTOT (BB * NN)          // 8192
#define SCALE 0.125f            // 1/sqrt(64)

// Scratch: Q (pre-scaled), K, V in [B, H, N, HD] layout
__device__ float g_Q[BB * HH * NN * HD];
__device__ float g_K[BB * HH * NN * HD];
__device__ float g_V[BB * HH * NN * HD];

// ---------------------------------------------------------------------------
// Kernel 1: QKV GEMM. out[m][e] = sum_k x[m][k] * w[e][k] + bias[e]
// 128x128 tile, BK=8, 8x8 per thread, 256 threads.
// Epilogue scatters to g_Q (scaled), g_K, g_V.
// ---------------------------------------------------------------------------
__global__ __launch_bounds__(256) void qkv_gemm_kernel(
    const float* __restrict__ x,     // [8192, 1024]
    const float* __restrict__ w,     // [3072, 1024]
    const float* __restrict__ bias)  // [3072]
{
    __shared__ __align__(16) float As[8 * 128];  // [k][m]
    __shared__ __align__(16) float Bs[8 * 128];  // [k][e]

    const int tid = threadIdx.x;
    const int tx = tid & 15;         // col group
    const int ty = tid >> 4;         // row group
    const int m0 = blockIdx.y * 128;
    const int e0 = blockIdx.x * 128;

    // global load indices: each thread loads one float4 per tile per operand
    const int ldRow = tid >> 1;          // 0..127
    const int ldK   = (tid & 1) * 4;     // 0 or 4

    float acc[8][8];
#pragma unroll
    for (int i = 0; i < 8; i++)
#pragma unroll
        for (int j = 0; j < 8; j++) acc[i][j] = 0.0f;

    for (int kt = 0; kt < DIM; kt += 8) {
        float4 av = *(const float4*)&x[(size_t)(m0 + ldRow) * DIM + kt + ldK];
        float4 bv = *(const float4*)&w[(size_t)(e0 + ldRow) * DIM + kt + ldK];
        As[(ldK + 0) * 128 + ldRow] = av.x;
        As[(ldK + 1) * 128 + ldRow] = av.y;
        As[(ldK + 2) * 128 + ldRow] = av.z;
        As[(ldK + 3) * 128 + ldRow] = av.w;
        Bs[(ldK + 0) * 128 + ldRow] = bv.x;
        Bs[(ldK + 1) * 128 + ldRow] = bv.y;
        Bs[(ldK + 2) * 128 + ldRow] = bv.z;
        Bs[(ldK + 3) * 128 + ldRow] = bv.w;
        __syncthreads();

#pragma unroll
        for (int k = 0; k < 8; k++) {
            float a[8], b[8];
            float4 a0 = *(const float4*)&As[k * 128 + ty * 8];
            float4 a1 = *(const float4*)&As[k * 128 + ty * 8 + 4];
            float4 b0 = *(const float4*)&Bs[k * 128 + tx * 8];
            float4 b1 = *(const float4*)&Bs[k * 128 + tx * 8 + 4];
            a[0]=a0.x; a[1]=a0.y; a[2]=a0.z; a[3]=a0.w;
            a[4]=a1.x; a[5]=a1.y; a[6]=a1.z; a[7]=a1.w;
            b[0]=b0.x; b[1]=b0.y; b[2]=b0.z; b[3]=b0.w;
            b[4]=b1.x; b[5]=b1.y; b[6]=b1.z; b[7]=b1.w;
#pragma unroll
            for (int i = 0; i < 8; i++)
#pragma unroll
                for (int j = 0; j < 8; j++)
                    acc[i][j] = fmaf(a[i], b[j], acc[i][j]);
        }
        __syncthreads();
    }

    // Epilogue: bias + scatter to [B,H,N,HD] with Q pre-scaled.
#pragma unroll
    for (int j = 0; j < 8; j++) {
        const int e  = e0 + tx * 8 + j;
        const int t  = e >> 10;              // 0:Q 1:K 2:V
        const int h  = (e >> 6) & (HH - 1);
        const int hd = e & (HD - 1);
        const float be = bias[e];
        float* dst = (t == 0) ? g_Q : (t == 1) ? g_K : g_V;
        const float mul = (t == 0) ? SCALE : 1.0f;
#pragma unroll
        for (int i = 0; i < 8; i++) {
            const int m = m0 + ty * 8 + i;
            const int b = m >> 11;           // /NN
            const int n = m & (NN - 1);
            dst[(size_t)((b * HH + h) * NN + n) * HD + hd] = (acc[i][j] + be) * mul;
        }
    }
}

// ---------------------------------------------------------------------------
// Kernel 2: Flash attention, fp32. One block = one (b,h) and one 64-row q-tile.
// 256 threads; thread (ty,tx) owns a 4x4 patch of S/P[q][k] and of O[q][d].
// Smem: Qs [d][q], BufA = K [d][k] then P [k][q], BufB = V [k][d]. 48 KB total.
// ---------------------------------------------------------------------------
__global__ __launch_bounds__(256) void attn_kernel(float* __restrict__ out)
{
    __shared__ __align__(16) float Qs[64 * 64];
    __shared__ __align__(16) float BufA[64 * 64];
    __shared__ __align__(16) float BufB[64 * 64];

    const int tid = threadIdx.x;
    const int tx = tid & 15, ty = tid >> 4;
    const int r0 = ty * 4, c0 = tx * 4;

    const int qt = blockIdx.x;   // 0..31
    const int h  = blockIdx.y;
    const int b  = blockIdx.z;
    const int q0 = qt * 64;

    const size_t base = (size_t)((b * HH + h) * NN) * HD;
    const float* Qg = g_Q + base;
    const float* Kg = g_K + base;
    const float* Vg = g_V + base;

    // Load Q tile transposed: Qs[d][q]
#pragma unroll
    for (int i = 0; i < 4; i++) {
        int id = tid + i * 256;
        int q  = id >> 4;
        int d  = (id & 15) << 2;
        float4 v = *(const float4*)&Qg[(size_t)(q0 + q) * HD + d];
        Qs[(d + 0) * 64 + q] = v.x;
        Qs[(d + 1) * 64 + q] = v.y;
        Qs[(d + 2) * 64 + q] = v.z;
        Qs[(d + 3) * 64 + q] = v.w;
    }

    float m_i[4], l_i[4];
    float o[4][4];
#pragma unroll
    for (int i = 0; i < 4; i++) {
        m_i[i] = -CUDART_INF_F;
        l_i[i] = 0.0f;
#pragma unroll
        for (int j = 0; j < 4; j++) o[i][j] = 0.0f;
    }

    for (int kt = 0; kt < NN / 64; kt++) {
        const int k0 = kt * 64;
        // Load K transposed [d][k] into BufA, V natural [k][d] into BufB
#pragma unroll
        for (int i = 0; i < 4; i++) {
            int id = tid + i * 256;
            int r  = id >> 4;
            int d  = (id & 15) << 2;
            float4 kv = *(const float4*)&Kg[(size_t)(k0 + r) * HD + d];
            BufA[(d + 0) * 64 + r] = kv.x;
            BufA[(d + 1) * 64 + r] = kv.y;
            BufA[(d + 2) * 64 + r] = kv.z;
            BufA[(d + 3) * 64 + r] = kv.w;
            float4 vv = *(const float4*)&Vg[(size_t)(k0 + r) * HD + d];
            *(float4*)&BufB[r * 64 + d] = vv;
        }
        __syncthreads();

        // S = Q . K^T  (dot over d)
        float s[4][4];
#pragma unroll
        for (int i = 0; i < 4; i++)
#pragma unroll
            for (int j = 0; j < 4; j++) s[i][j] = 0.0f;

#pragma unroll 8
        for (int d = 0; d < 64; d++) {
            float4 qa = *(const float4*)&Qs[d * 64 + r0];
            float4 kb = *(const float4*)&BufA[d * 64 + c0];
            float a[4] = {qa.x, qa.y, qa.z, qa.w};
            float bb[4] = {kb.x, kb.y, kb.z, kb.w};
#pragma unroll
            for (int i = 0; i < 4; i++)
#pragma unroll
                for (int j = 0; j < 4; j++)
                    s[i][j] = fmaf(a[i], bb[j], s[i][j]);
        }
        __syncthreads();  // everyone done reading K before P overwrites BufA

        // Online softmax update
        float rm[4], rs[4], alpha[4];
#pragma unroll
        for (int i = 0; i < 4; i++) {
            float v = fmaxf(fmaxf(s[i][0], s[i][1]), fmaxf(s[i][2], s[i][3]));
#pragma unroll
            for (int off = 8; off >= 1; off >>= 1)
                v = fmaxf(v, __shfl_xor_sync(0xffffffffu, v, off));
            rm[i] = v;
            float mnew = fmaxf(m_i[i], v);
            alpha[i] = __expf(m_i[i] - mnew);
            m_i[i] = mnew;
        }
#pragma unroll
        for (int i = 0; i < 4; i++) {
            float sum = 0.0f;
#pragma unroll
            for (int j = 0; j < 4; j++) {
                s[i][j] = __expf(s[i][j] - m_i[i]);   // now P
                sum += s[i][j];
            }
#pragma unroll
            for (int off = 8; off >= 1; off >>= 1)
                sum += __shfl_xor_sync(0xffffffffu, sum, off);
            rs[i] = sum;
            l_i[i] = l_i[i] * alpha[i] + rs[i];
#pragma unroll
            for (int j = 0; j < 4; j++) o[i][j] *= alpha[i];
        }

        // Store P transposed into BufA as [k][q]
#pragma unroll
        for (int i = 0; i < 4; i++)
#pragma unroll
            for (int j = 0; j < 4; j++)
                BufA[(c0 + j) * 64 + (r0 + i)] = s[i][j];
        __syncthreads();

        // O += P . V   (sum over k)
#pragma unroll 8
        for (int k = 0; k < 64; k++) {
            float4 pv = *(const float4*)&BufA[k * 64 + r0];
            float4 vv = *(const float4*)&BufB[k * 64 + c0];
            float p[4] = {pv.x, pv.y, pv.z, pv.w};
            float v[4] = {vv.x, vv.y, vv.z, vv.w};
#pragma unroll
            for (int i = 0; i < 4; i++)
#pragma unroll
                for (int j = 0; j < 4; j++)
                    o[i][j] = fmaf(p[i], v[j], o[i][j]);
        }
        __syncthreads();  // before next tile overwrites BufA/BufB
    }

    // Write out: [B, N, H*HD]
#pragma unroll
    for (int i = 0; i < 4; i++) {
        const float inv = 1.0f / l_i[i];
        const int q = q0 + r0 + i;
        float4 res;
        res.x = o[i][0] * inv;
        res.y = o[i][1] * inv;
        res.z = o[i][2] * inv;
        res.w = o[i][3] * inv;
        *(float4*)&out[(size_t)(b * NN + q) * DIM + h * HD + c0] = res;
    }
}

// ---------------------------------------------------------------------------
extern "C" void kernel_launch(void* const* d_in, const int* in_sizes, int n_in,
                              void* d_out, int out_size)
{
    const float* x    = (const float*)d_in[0];
    const float* w    = (const float*)d_in[1];
    const float* bias = (const float*)d_in[2];
    float* out = (float*)d_out;

    dim3 g1(E3 / 128, MTOT / 128);   // 24 x 64
    qkv_gemm_kernel<<<g1, 256>>>(x, w, bias);

    dim3 g2(NN / 64, HH, BB);        // 32 x 16 x 4
    attn_kernel<<<g2, 256>>>(out);
}